// round 1
// baseline (speedup 1.0000x reference)
#include <cuda_runtime.h>
#include <math.h>

#define N_NODES_MAX 100000
#define D1 64
#define D2 32

// Scratch (no allocations allowed): aggregation buffer, layer-1 output, degree.
__device__ float g_agg[(size_t)N_NODES_MAX * D1];
__device__ float g_x1 [(size_t)N_NODES_MAX * D1];
__device__ float g_deg[N_NODES_MAX];

// ---------------------------------------------------------------------------
// Zero two buffers in one kernel.
__global__ void zero2_kernel(float* __restrict__ a, int na,
                             float* __restrict__ b, int nb) {
    int i = blockIdx.x * blockDim.x + threadIdx.x;
    int stride = gridDim.x * blockDim.x;
    for (int j = i; j < na; j += stride) a[j] = 0.0f;
    if (b) for (int j = i; j < nb; j += stride) b[j] = 0.0f;
}

// ---------------------------------------------------------------------------
// Edge scatter: 16 threads per edge, each moving a float4 (64 floats/edge).
// Uses sm_90+ vector reduction red.global.add.v4.f32 (4x fewer atomic ops).
__global__ void __launch_bounds__(256)
scatter_kernel(const float* __restrict__ x,
               const int*   __restrict__ src,
               const int*   __restrict__ dst,
               float*       __restrict__ agg,
               float*       __restrict__ deg,   // null for layer 2
               int E) {
    int t = blockIdx.x * blockDim.x + threadIdx.x;
    int e = t >> 4;
    int lane = t & 15;
    if (e >= E) return;
    int s = __ldg(&src[e]);
    int d = __ldg(&dst[e]);
    float4 v = reinterpret_cast<const float4*>(x + (size_t)s * D1)[lane];
    float* ap = agg + (size_t)d * D1 + lane * 4;
    asm volatile("red.global.add.v4.f32 [%0], {%1,%2,%3,%4};"
                 :: "l"(ap), "f"(v.x), "f"(v.y), "f"(v.z), "f"(v.w)
                 : "memory");
    if (deg != nullptr && lane == 0) atomicAdd(&deg[d], 1.0f);
}

// ---------------------------------------------------------------------------
// Layer-1 node update: y = relu((agg/max(deg,1)) @ W1 + b1), [N,64]x[64,64].
// One thread per node; W1 in shared (broadcast LDS.128).
__global__ void __launch_bounds__(256)
update1_kernel(const float* __restrict__ agg,
               const float* __restrict__ deg,
               const float* __restrict__ W1,   // [64,64] row-major (k, j)
               const float* __restrict__ b1,   // [64]
               float*       __restrict__ out,  // [N,64]
               int N) {
    __shared__ float Ws[D1 * D1];
    __shared__ float bs[D1];
    for (int i = threadIdx.x; i < D1 * D1; i += blockDim.x) Ws[i] = W1[i];
    if (threadIdx.x < D1) bs[threadIdx.x] = b1[threadIdx.x];
    __syncthreads();

    int node = blockIdx.x * blockDim.x + threadIdx.x;
    if (node >= N) return;

    float inv = 1.0f / fmaxf(deg[node], 1.0f);
    float in[D1];
    const float4* ar = reinterpret_cast<const float4*>(agg + (size_t)node * D1);
#pragma unroll
    for (int i = 0; i < D1 / 4; i++) {
        float4 v = ar[i];
        in[i * 4 + 0] = v.x * inv;
        in[i * 4 + 1] = v.y * inv;
        in[i * 4 + 2] = v.z * inv;
        in[i * 4 + 3] = v.w * inv;
    }

    float4* orow = reinterpret_cast<float4*>(out + (size_t)node * D1);
    for (int j = 0; j < D1; j += 4) {
        float a0 = bs[j + 0], a1 = bs[j + 1], a2 = bs[j + 2], a3 = bs[j + 3];
#pragma unroll
        for (int k = 0; k < D1; k++) {
            float xk = in[k];
            const float4 w = *reinterpret_cast<const float4*>(&Ws[k * D1 + j]);
            a0 = fmaf(xk, w.x, a0);
            a1 = fmaf(xk, w.y, a1);
            a2 = fmaf(xk, w.z, a2);
            a3 = fmaf(xk, w.w, a3);
        }
        float4 o;
        o.x = fmaxf(a0, 0.0f); o.y = fmaxf(a1, 0.0f);
        o.z = fmaxf(a2, 0.0f); o.w = fmaxf(a3, 0.0f);
        orow[j / 4] = o;
    }
}

// ---------------------------------------------------------------------------
// Layer-2 node update + readout:
// h = relu((agg/max(deg,1)) @ W2 + b2)  [N,32]
// out = sigmoid(mean(h) * Wd + bd)      [N,1]
__global__ void __launch_bounds__(256)
update2_kernel(const float* __restrict__ agg,
               const float* __restrict__ deg,
               const float* __restrict__ W2,   // [64,32] row-major (k, j)
               const float* __restrict__ b2,   // [32]
               const float* __restrict__ Wd,   // [1,1]
               const float* __restrict__ bd,   // [1]
               float*       __restrict__ out,  // [N]
               int N) {
    __shared__ float Ws[D1 * D2];
    __shared__ float bs[D2];
    for (int i = threadIdx.x; i < D1 * D2; i += blockDim.x) Ws[i] = W2[i];
    if (threadIdx.x < D2) bs[threadIdx.x] = b2[threadIdx.x];
    __syncthreads();

    int node = blockIdx.x * blockDim.x + threadIdx.x;
    if (node >= N) return;

    float inv = 1.0f / fmaxf(deg[node], 1.0f);
    float in[D1];
    const float4* ar = reinterpret_cast<const float4*>(agg + (size_t)node * D1);
#pragma unroll
    for (int i = 0; i < D1 / 4; i++) {
        float4 v = ar[i];
        in[i * 4 + 0] = v.x * inv;
        in[i * 4 + 1] = v.y * inv;
        in[i * 4 + 2] = v.z * inv;
        in[i * 4 + 3] = v.w * inv;
    }

    float sum = 0.0f;
    for (int j = 0; j < D2; j += 4) {
        float a0 = bs[j + 0], a1 = bs[j + 1], a2 = bs[j + 2], a3 = bs[j + 3];
#pragma unroll
        for (int k = 0; k < D1; k++) {
            float xk = in[k];
            const float4 w = *reinterpret_cast<const float4*>(&Ws[k * D2 + j]);
            a0 = fmaf(xk, w.x, a0);
            a1 = fmaf(xk, w.y, a1);
            a2 = fmaf(xk, w.z, a2);
            a3 = fmaf(xk, w.w, a3);
        }
        sum += fmaxf(a0, 0.0f) + fmaxf(a1, 0.0f) + fmaxf(a2, 0.0f) + fmaxf(a3, 0.0f);
    }

    float m = sum * (1.0f / (float)D2);
    float z = fmaf(m, Wd[0], bd[0]);
    out[node] = 1.0f / (1.0f + expf(-z));
}

// ---------------------------------------------------------------------------
extern "C" void kernel_launch(void* const* d_in, const int* in_sizes, int n_in,
                              void* d_out, int out_size) {
    const float* x   = (const float*)d_in[0];
    const int*   src = (const int*)  d_in[1];
    const int*   dst = (const int*)  d_in[2];
    const float* W1  = (const float*)d_in[3];
    const float* b1  = (const float*)d_in[4];
    const float* W2  = (const float*)d_in[5];
    const float* b2  = (const float*)d_in[6];
    const float* Wd  = (const float*)d_in[7];
    const float* bd  = (const float*)d_in[8];
    float* out = (float*)d_out;

    const int N = in_sizes[0] / D1;
    const int E = in_sizes[1];

    float *agg, *x1, *deg;
    cudaGetSymbolAddress((void**)&agg, g_agg);
    cudaGetSymbolAddress((void**)&x1,  g_x1);
    cudaGetSymbolAddress((void**)&deg, g_deg);

    const int naggf = N * D1;

    // zero agg + deg
    {
        int threads = 256, blocks = 2048;
        zero2_kernel<<<blocks, threads>>>(agg, naggf, deg, N);
    }
    // layer-1 scatter (also builds deg)
    {
        int threads = 256;
        long long tot = (long long)E * 16;
        int blocks = (int)((tot + threads - 1) / threads);
        scatter_kernel<<<blocks, threads>>>(x, src, dst, agg, deg, E);
    }
    // layer-1 node update -> x1
    {
        int threads = 256, blocks = (N + threads - 1) / threads;
        update1_kernel<<<blocks, threads>>>(agg, deg, W1, b1, x1, N);
    }
    // zero agg again
    {
        zero2_kernel<<<2048, 256>>>(agg, naggf, nullptr, 0);
    }
    // layer-2 scatter
    {
        int threads = 256;
        long long tot = (long long)E * 16;
        int blocks = (int)((tot + threads - 1) / threads);
        scatter_kernel<<<blocks, threads>>>(x1, src, dst, agg, nullptr, E);
    }
    // layer-2 update + readout
    {
        int threads = 256, blocks = (N + threads - 1) / threads;
        update2_kernel<<<blocks, threads>>>(agg, deg, W2, b2, Wd, bd, out, N);
    }
}

// round 2
// speedup vs baseline: 1.3293x; 1.3293x over previous
#include <cuda_runtime.h>
#include <math.h>

#define N_NODES_MAX 100000
#define E_MAX       1600000
#define D1 64
#define D2 32
#define SCAN_B 256
#define MAX_BLOCKS_SCAN 1024   // ceil(100000/256)=391 <= 1024

// Scratch (no allocations allowed)
__device__ float g_x1 [(size_t)N_NODES_MAX * D1];  // layer-1 output
__device__ int   g_cnt [N_NODES_MAX];              // degree histogram
__device__ int   g_row [N_NODES_MAX + 1];          // CSR row offsets
__device__ int   g_cur [N_NODES_MAX];              // fill cursors
__device__ int   g_csr [E_MAX];                    // CSR src indices (sorted by dst)
__device__ int   g_bsum[MAX_BLOCKS_SCAN];
__device__ int   g_boff[MAX_BLOCKS_SCAN];

// ---------------------------------------------------------------------------
// Degree histogram over edge destinations.
__global__ void hist_kernel(const int* __restrict__ dst, int* __restrict__ cnt, int E) {
    int i = blockIdx.x * blockDim.x + threadIdx.x;
    if (i < E) atomicAdd(&cnt[dst[i]], 1);
}

// ---------------------------------------------------------------------------
// Exclusive scan, stage 1: per-block Hillis-Steele.
__global__ void scan1_kernel(const int* __restrict__ cnt, int* __restrict__ row,
                             int* __restrict__ bsum, int N) {
    __shared__ int s[SCAN_B];
    int i = blockIdx.x * SCAN_B + threadIdx.x;
    int v = (i < N) ? cnt[i] : 0;
    s[threadIdx.x] = v;
    __syncthreads();
#pragma unroll
    for (int off = 1; off < SCAN_B; off <<= 1) {
        int t = 0;
        if (threadIdx.x >= off) t = s[threadIdx.x - off];
        __syncthreads();
        if (threadIdx.x >= off) s[threadIdx.x] += t;
        __syncthreads();
    }
    int incl = s[threadIdx.x];
    if (i < N) row[i] = incl - v;                 // exclusive within block
    if (threadIdx.x == SCAN_B - 1) bsum[blockIdx.x] = incl;  // block total
}

// Stage 2: single block scans the block sums (exclusive).
__global__ void scan2_kernel(const int* __restrict__ bsum, int* __restrict__ boff, int nb) {
    __shared__ int s[MAX_BLOCKS_SCAN];
    int t = threadIdx.x;
    int v = (t < nb) ? bsum[t] : 0;
    s[t] = v;
    __syncthreads();
#pragma unroll
    for (int off = 1; off < MAX_BLOCKS_SCAN; off <<= 1) {
        int u = 0;
        if (t >= off) u = s[t - off];
        __syncthreads();
        if (t >= off) s[t] += u;
        __syncthreads();
    }
    if (t < nb) boff[t] = s[t] - v;
}

// Stage 3: add block offsets; initialize cursors; cap row[N]=E.
__global__ void scan3_kernel(int* __restrict__ row, int* __restrict__ cur,
                             const int* __restrict__ boff, int N, int E) {
    int i = blockIdx.x * blockDim.x + threadIdx.x;
    if (i < N) {
        int r = row[i] + boff[i / SCAN_B];
        row[i] = r;
        cur[i] = r;
    }
    if (i == 0) row[N] = E;
}

// ---------------------------------------------------------------------------
// CSR fill: slot each edge's src into its destination's segment.
__global__ void fill_kernel(const int* __restrict__ src, const int* __restrict__ dst,
                            int* __restrict__ cur, int* __restrict__ csr, int E) {
    int i = blockIdx.x * blockDim.x + threadIdx.x;
    if (i < E) {
        int d = dst[i];
        int p = atomicAdd(&cur[d], 1);
        csr[p] = src[i];
    }
}

// ---------------------------------------------------------------------------
// Fused layer 1: gather(mean) + [64x64] GEMM + bias + ReLU.
// Half-warp (16 lanes) per node: each lane gathers one float4 (4 features),
// stages the 64-vector in smem, then computes 4 outputs.
__global__ void __launch_bounds__(512)
layer1_kernel(const float* __restrict__ x,
              const int*   __restrict__ csr,
              const int*   __restrict__ row,
              const float* __restrict__ W1,   // [64,64] (k, j)
              const float* __restrict__ b1,
              float*       __restrict__ out,  // [N,64]
              int N) {
    __shared__ float Ws[D1 * D1];
    __shared__ float bs[D1];
    __shared__ float in_s[32][D1];   // 32 half-warps per block

    for (int i = threadIdx.x; i < D1 * D1; i += blockDim.x) Ws[i] = W1[i];
    if (threadIdx.x < D1) bs[threadIdx.x] = b1[threadIdx.x];
    __syncthreads();

    int hw = threadIdx.x >> 4;
    int lane = threadIdx.x & 15;
    int node = blockIdx.x * 32 + hw;
    if (node >= N) node = N - 1;   // duplicates recompute identical values

    int beg = row[node], end = row[node + 1];
    const float4* x4 = reinterpret_cast<const float4*>(x);

    float4 a0 = make_float4(0.f, 0.f, 0.f, 0.f);
    float4 a1 = a0, a2 = a0, a3 = a0;
    int e = beg;
    for (; e + 3 < end; e += 4) {
        int s0 = csr[e], s1 = csr[e + 1], s2 = csr[e + 2], s3 = csr[e + 3];
        float4 v0 = x4[(size_t)s0 * 16 + lane];
        float4 v1 = x4[(size_t)s1 * 16 + lane];
        float4 v2 = x4[(size_t)s2 * 16 + lane];
        float4 v3 = x4[(size_t)s3 * 16 + lane];
        a0.x += v0.x; a0.y += v0.y; a0.z += v0.z; a0.w += v0.w;
        a1.x += v1.x; a1.y += v1.y; a1.z += v1.z; a1.w += v1.w;
        a2.x += v2.x; a2.y += v2.y; a2.z += v2.z; a2.w += v2.w;
        a3.x += v3.x; a3.y += v3.y; a3.z += v3.z; a3.w += v3.w;
    }
    for (; e < end; e++) {
        int s0 = csr[e];
        float4 v0 = x4[(size_t)s0 * 16 + lane];
        a0.x += v0.x; a0.y += v0.y; a0.z += v0.z; a0.w += v0.w;
    }
    float inv = 1.0f / fmaxf((float)(end - beg), 1.0f);
    float4 a;
    a.x = (a0.x + a1.x + a2.x + a3.x) * inv;
    a.y = (a0.y + a1.y + a2.y + a3.y) * inv;
    a.z = (a0.z + a1.z + a2.z + a3.z) * inv;
    a.w = (a0.w + a1.w + a2.w + a3.w) * inv;

    reinterpret_cast<float4*>(&in_s[hw][0])[lane] = a;
    __syncwarp();

    int j = lane * 4;
    float o0 = bs[j + 0], o1 = bs[j + 1], o2 = bs[j + 2], o3 = bs[j + 3];
#pragma unroll
    for (int k = 0; k < D1; k++) {
        float xk = in_s[hw][k];
        float4 w = *reinterpret_cast<const float4*>(&Ws[k * D1 + j]);
        o0 = fmaf(xk, w.x, o0);
        o1 = fmaf(xk, w.y, o1);
        o2 = fmaf(xk, w.z, o2);
        o3 = fmaf(xk, w.w, o3);
    }
    float4 o;
    o.x = fmaxf(o0, 0.f); o.y = fmaxf(o1, 0.f);
    o.z = fmaxf(o2, 0.f); o.w = fmaxf(o3, 0.f);
    reinterpret_cast<float4*>(out + (size_t)node * D1)[lane] = o;
}

// ---------------------------------------------------------------------------
// Fused layer 2 + readout: gather(mean) + [64x32] GEMM + bias + ReLU +
// mean over features + sigmoid(x*Wd + bd).
__global__ void __launch_bounds__(512)
layer2_kernel(const float* __restrict__ x,    // g_x1 [N,64]
              const int*   __restrict__ csr,
              const int*   __restrict__ row,
              const float* __restrict__ W2,   // [64,32] (k, j)
              const float* __restrict__ b2,
              const float* __restrict__ Wd,
              const float* __restrict__ bd,
              float*       __restrict__ out,  // [N]
              int N) {
    __shared__ float Ws[D1 * D2];
    __shared__ float bs[D2];
    __shared__ float in_s[32][D1];

    for (int i = threadIdx.x; i < D1 * D2; i += blockDim.x) Ws[i] = W2[i];
    if (threadIdx.x < D2) bs[threadIdx.x] = b2[threadIdx.x];
    __syncthreads();

    int hw = threadIdx.x >> 4;
    int lane = threadIdx.x & 15;
    int node = blockIdx.x * 32 + hw;
    if (node >= N) node = N - 1;

    int beg = row[node], end = row[node + 1];
    const float4* x4 = reinterpret_cast<const float4*>(x);

    float4 a0 = make_float4(0.f, 0.f, 0.f, 0.f);
    float4 a1 = a0, a2 = a0, a3 = a0;
    int e = beg;
    for (; e + 3 < end; e += 4) {
        int s0 = csr[e], s1 = csr[e + 1], s2 = csr[e + 2], s3 = csr[e + 3];
        float4 v0 = x4[(size_t)s0 * 16 + lane];
        float4 v1 = x4[(size_t)s1 * 16 + lane];
        float4 v2 = x4[(size_t)s2 * 16 + lane];
        float4 v3 = x4[(size_t)s3 * 16 + lane];
        a0.x += v0.x; a0.y += v0.y; a0.z += v0.z; a0.w += v0.w;
        a1.x += v1.x; a1.y += v1.y; a1.z += v1.z; a1.w += v1.w;
        a2.x += v2.x; a2.y += v2.y; a2.z += v2.z; a2.w += v2.w;
        a3.x += v3.x; a3.y += v3.y; a3.z += v3.z; a3.w += v3.w;
    }
    for (; e < end; e++) {
        int s0 = csr[e];
        float4 v0 = x4[(size_t)s0 * 16 + lane];
        a0.x += v0.x; a0.y += v0.y; a0.z += v0.z; a0.w += v0.w;
    }
    float inv = 1.0f / fmaxf((float)(end - beg), 1.0f);
    float4 a;
    a.x = (a0.x + a1.x + a2.x + a3.x) * inv;
    a.y = (a0.y + a1.y + a2.y + a3.y) * inv;
    a.z = (a0.z + a1.z + a2.z + a3.z) * inv;
    a.w = (a0.w + a1.w + a2.w + a3.w) * inv;

    reinterpret_cast<float4*>(&in_s[hw][0])[lane] = a;
    __syncwarp();

    int j = lane * 2;
    float o0 = bs[j + 0], o1 = bs[j + 1];
#pragma unroll
    for (int k = 0; k < D1; k++) {
        float xk = in_s[hw][k];
        float2 w = *reinterpret_cast<const float2*>(&Ws[k * D2 + j]);
        o0 = fmaf(xk, w.x, o0);
        o1 = fmaf(xk, w.y, o1);
    }
    float v = fmaxf(o0, 0.f) + fmaxf(o1, 0.f);
    // reduce across the 16-lane half-warp
#pragma unroll
    for (int off = 8; off > 0; off >>= 1)
        v += __shfl_down_sync(0xffffffffu, v, off, 16);

    if (lane == 0) {
        float m = v * (1.0f / (float)D2);
        float z = fmaf(m, Wd[0], bd[0]);
        out[node] = 1.0f / (1.0f + expf(-z));
    }
}

// ---------------------------------------------------------------------------
extern "C" void kernel_launch(void* const* d_in, const int* in_sizes, int n_in,
                              void* d_out, int out_size) {
    const float* x   = (const float*)d_in[0];
    const int*   src = (const int*)  d_in[1];
    const int*   dst = (const int*)  d_in[2];
    const float* W1  = (const float*)d_in[3];
    const float* b1  = (const float*)d_in[4];
    const float* W2  = (const float*)d_in[5];
    const float* b2  = (const float*)d_in[6];
    const float* Wd  = (const float*)d_in[7];
    const float* bd  = (const float*)d_in[8];
    float* out = (float*)d_out;

    const int N = in_sizes[0] / D1;
    const int E = in_sizes[1];

    float *x1;
    int *cnt, *row, *cur, *csr, *bsum, *boff;
    cudaGetSymbolAddress((void**)&x1,   g_x1);
    cudaGetSymbolAddress((void**)&cnt,  g_cnt);
    cudaGetSymbolAddress((void**)&row,  g_row);
    cudaGetSymbolAddress((void**)&cur,  g_cur);
    cudaGetSymbolAddress((void**)&csr,  g_csr);
    cudaGetSymbolAddress((void**)&bsum, g_bsum);
    cudaGetSymbolAddress((void**)&boff, g_boff);

    const int nb = (N + SCAN_B - 1) / SCAN_B;

    // --- CSR build ---
    cudaMemsetAsync(cnt, 0, (size_t)N * sizeof(int));
    hist_kernel<<<(E + 255) / 256, 256>>>(dst, cnt, E);
    scan1_kernel<<<nb, SCAN_B>>>(cnt, row, bsum, N);
    scan2_kernel<<<1, MAX_BLOCKS_SCAN>>>(bsum, boff, nb);
    scan3_kernel<<<(N + 255) / 256, 256>>>(row, cur, boff, N, E);
    fill_kernel<<<(E + 255) / 256, 256>>>(src, dst, cur, csr, E);

    // --- fused layers ---
    int blocks = (N + 31) / 32;
    layer1_kernel<<<blocks, 512>>>(x, csr, row, W1, b1, x1, N);
    layer2_kernel<<<blocks, 512>>>(x1, csr, row, W2, b2, Wd, bd, out, N);
}